// round 2
// baseline (speedup 1.0000x reference)
#include <cuda_runtime.h>
#include <cuda_bf16.h>
#include <cstdint>
#include <cstdio>

// Problem constants
#define BB 4
#define LL 2048
#define DD 1024
#define HH 16
#define DKK 64
#define DFF 4096
#define MROWS (BB*LL)          // 8192
#define ATTN_OFF ((size_t)MROWS*DD)  // y region elems = 8388608

// Scratch (device globals; no allocation allowed)
__device__ float g_x[(size_t)MROWS*DD];    // LN1 out
__device__ float g_q[(size_t)MROWS*DD];
__device__ float g_k[(size_t)MROWS*DD];
__device__ float g_v[(size_t)MROWS*DD];
__device__ float g_o[(size_t)MROWS*DD];    // attn @ V, [b,l,h*dv]
__device__ float g_y1[(size_t)MROWS*DD];   // after attention residual
__device__ float g_z[(size_t)MROWS*DD];    // LN2 out
__device__ float g_h[(size_t)MROWS*DFF];   // FFN hidden

// ---------------------------------------------------------------------------
// LayerNorm: one block per row, 256 threads, D=1024
// ---------------------------------------------------------------------------
__global__ void __launch_bounds__(256) ln_kernel(const float* __restrict__ in,
                                                 const float* __restrict__ gamma,
                                                 const float* __restrict__ beta,
                                                 float* __restrict__ out) {
    int row = blockIdx.x;
    const float* x = in + (size_t)row * DD;
    float* y = out + (size_t)row * DD;
    int t = threadIdx.x;
    float v[4];
    float s = 0.f;
#pragma unroll
    for (int i = 0; i < 4; i++) { v[i] = x[t + 256 * i]; s += v[i]; }
    __shared__ float red[32];
#pragma unroll
    for (int o = 16; o; o >>= 1) s += __shfl_xor_sync(0xffffffffu, s, o);
    if ((t & 31) == 0) red[t >> 5] = s;
    __syncthreads();
    if (t < 32) {
        float z = (t < 8) ? red[t] : 0.f;
#pragma unroll
        for (int o = 4; o; o >>= 1) z += __shfl_xor_sync(0xffffffffu, z, o);
        if (t == 0) red[0] = z;
    }
    __syncthreads();
    float mu = red[0] * (1.f / DD);
    __syncthreads();
    float s2 = 0.f;
#pragma unroll
    for (int i = 0; i < 4; i++) { float d = v[i] - mu; s2 += d * d; }
#pragma unroll
    for (int o = 16; o; o >>= 1) s2 += __shfl_xor_sync(0xffffffffu, s2, o);
    if ((t & 31) == 0) red[t >> 5] = s2;
    __syncthreads();
    if (t < 32) {
        float z = (t < 8) ? red[t] : 0.f;
#pragma unroll
        for (int o = 4; o; o >>= 1) z += __shfl_xor_sync(0xffffffffu, z, o);
        if (t == 0) red[0] = z;
    }
    __syncthreads();
    float rstd = rsqrtf(red[0] * (1.f / DD) + 1e-6f);
#pragma unroll
    for (int i = 0; i < 4; i++) {
        int c = t + 256 * i;
        y[c] = (v[i] - mu) * rstd * gamma[c] + beta[c];
    }
}

// ---------------------------------------------------------------------------
// Generic C[M,N] = A[M,K] * B[N,K]^T, 128x128x16 tiles, 8x8 per thread.
// EPI: 0 none, 1 relu(bias+acc), 2 acc+bias+res, 3 acc+res
// ---------------------------------------------------------------------------
template <int EPI>
__global__ void __launch_bounds__(256) gemm_abt(
    const float* __restrict__ A, int lda,
    const float* __restrict__ Bm, int ldb,
    float* __restrict__ C, int ldc,
    int K,
    const float* __restrict__ bias,
    const float* __restrict__ res, int ldres) {
    int bm = blockIdx.y * 128;
    int bn = blockIdx.x * 128;
    __shared__ float As[16][128];
    __shared__ float Bs[16][128];
    int tid = threadIdx.x;
    int tx = tid & 15, ty = tid >> 4;
    float acc[8][8];
#pragma unroll
    for (int i = 0; i < 8; i++)
#pragma unroll
        for (int j = 0; j < 8; j++) acc[i][j] = 0.f;

    for (int k0 = 0; k0 < K; k0 += 16) {
#pragma unroll
        for (int i = 0; i < 2; i++) {
            int f = tid + i * 256;     // 0..511
            int row = f >> 2;          // 0..127
            int c4 = (f & 3) << 2;     // 0,4,8,12
            float4 va = *(const float4*)(A + (size_t)(bm + row) * lda + k0 + c4);
            As[c4 + 0][row] = va.x; As[c4 + 1][row] = va.y;
            As[c4 + 2][row] = va.z; As[c4 + 3][row] = va.w;
            float4 vb = *(const float4*)(Bm + (size_t)(bn + row) * ldb + k0 + c4);
            Bs[c4 + 0][row] = vb.x; Bs[c4 + 1][row] = vb.y;
            Bs[c4 + 2][row] = vb.z; Bs[c4 + 3][row] = vb.w;
        }
        __syncthreads();
#pragma unroll
        for (int kk = 0; kk < 16; kk++) {
            float4 a0 = *(const float4*)&As[kk][ty * 8];
            float4 a1 = *(const float4*)&As[kk][ty * 8 + 4];
            float4 b0 = *(const float4*)&Bs[kk][tx * 8];
            float4 b1 = *(const float4*)&Bs[kk][tx * 8 + 4];
            float a[8] = {a0.x, a0.y, a0.z, a0.w, a1.x, a1.y, a1.z, a1.w};
            float b[8] = {b0.x, b0.y, b0.z, b0.w, b1.x, b1.y, b1.z, b1.w};
#pragma unroll
            for (int i = 0; i < 8; i++)
#pragma unroll
                for (int j = 0; j < 8; j++) acc[i][j] += a[i] * b[j];
        }
        __syncthreads();
    }
#pragma unroll
    for (int i = 0; i < 8; i++) {
        int m = bm + ty * 8 + i;
#pragma unroll
        for (int j = 0; j < 8; j++) {
            int n = bn + tx * 8 + j;
            float v = acc[i][j];
            if (EPI == 1) v = fmaxf(v + bias[n], 0.f);
            if (EPI == 2) v = v + bias[n] + res[(size_t)m * ldres + n];
            if (EPI == 3) v = v + res[(size_t)m * ldres + n];
            C[(size_t)m * ldc + n] = v;
        }
    }
}

// ---------------------------------------------------------------------------
// Attention scores: per (b,h) S = (Q Kt)/8 * prior, masked -> attn region
// grid (16,16,64)
// ---------------------------------------------------------------------------
__global__ void __launch_bounds__(256) scores_kernel(
    const float* __restrict__ q, const float* __restrict__ k,
    const float* __restrict__ prior, const int* __restrict__ mask,
    float* __restrict__ attn) {
    int z = blockIdx.z;
    int b = z >> 4, h = z & 15;
    const float* A = q + (size_t)b * LL * DD + h * DKK;
    const float* Bm = k + (size_t)b * LL * DD + h * DKK;
    float* Cp = attn + (size_t)z * LL * LL;
    int bm = blockIdx.y * 128;
    int bn = blockIdx.x * 128;
    __shared__ float As[16][128];
    __shared__ float Bs[16][128];
    int tid = threadIdx.x;
    int tx = tid & 15, ty = tid >> 4;
    float acc[8][8];
#pragma unroll
    for (int i = 0; i < 8; i++)
#pragma unroll
        for (int j = 0; j < 8; j++) acc[i][j] = 0.f;

    for (int k0 = 0; k0 < DKK; k0 += 16) {
#pragma unroll
        for (int i = 0; i < 2; i++) {
            int f = tid + i * 256;
            int row = f >> 2;
            int c4 = (f & 3) << 2;
            float4 va = *(const float4*)(A + (size_t)(bm + row) * DD + k0 + c4);
            As[c4 + 0][row] = va.x; As[c4 + 1][row] = va.y;
            As[c4 + 2][row] = va.z; As[c4 + 3][row] = va.w;
            float4 vb = *(const float4*)(Bm + (size_t)(bn + row) * DD + k0 + c4);
            Bs[c4 + 0][row] = vb.x; Bs[c4 + 1][row] = vb.y;
            Bs[c4 + 2][row] = vb.z; Bs[c4 + 3][row] = vb.w;
        }
        __syncthreads();
#pragma unroll
        for (int kk = 0; kk < 16; kk++) {
            float4 a0 = *(const float4*)&As[kk][ty * 8];
            float4 a1 = *(const float4*)&As[kk][ty * 8 + 4];
            float4 b0 = *(const float4*)&Bs[kk][tx * 8];
            float4 b1 = *(const float4*)&Bs[kk][tx * 8 + 4];
            float a[8] = {a0.x, a0.y, a0.z, a0.w, a1.x, a1.y, a1.z, a1.w};
            float b2[8] = {b0.x, b0.y, b0.z, b0.w, b1.x, b1.y, b1.z, b1.w};
#pragma unroll
            for (int i = 0; i < 8; i++)
#pragma unroll
                for (int j = 0; j < 8; j++) acc[i][j] += a[i] * b2[j];
        }
        __syncthreads();
    }
    int msk[8];
#pragma unroll
    for (int j = 0; j < 8; j++) msk[j] = mask[b * LL + bn + tx * 8 + j];
#pragma unroll
    for (int i = 0; i < 8; i++) {
        int m = bm + ty * 8 + i;
        const float* prow = prior + ((size_t)b * LL + m) * LL + bn + tx * 8;
        float* crow = Cp + (size_t)m * LL + bn + tx * 8;
#pragma unroll
        for (int j = 0; j < 8; j++) {
            float v = acc[i][j] * 0.125f * prow[j];
            if (msk[j] == 0) v = -1e9f;
            crow[j] = v;
        }
    }
}

// ---------------------------------------------------------------------------
// Row softmax over 2048 keys, in-place in attn region. grid = B*H*L blocks
// ---------------------------------------------------------------------------
__global__ void __launch_bounds__(256) softmax_kernel(float* __restrict__ attn) {
    size_t row = blockIdx.x;
    float* p = attn + row * LL;
    int t = threadIdx.x;
    float v[8];
    float mx = -3.4e38f;
#pragma unroll
    for (int i = 0; i < 8; i++) { v[i] = p[t + 256 * i]; mx = fmaxf(mx, v[i]); }
    __shared__ float red[32];
#pragma unroll
    for (int o = 16; o; o >>= 1) mx = fmaxf(mx, __shfl_xor_sync(0xffffffffu, mx, o));
    if ((t & 31) == 0) red[t >> 5] = mx;
    __syncthreads();
    if (t < 32) {
        float z = (t < 8) ? red[t] : -3.4e38f;
#pragma unroll
        for (int o = 4; o; o >>= 1) z = fmaxf(z, __shfl_xor_sync(0xffffffffu, z, o));
        if (t == 0) red[0] = z;
    }
    __syncthreads();
    mx = red[0];
    __syncthreads();
    float s = 0.f;
#pragma unroll
    for (int i = 0; i < 8; i++) { v[i] = expf(v[i] - mx); s += v[i]; }
#pragma unroll
    for (int o = 16; o; o >>= 1) s += __shfl_xor_sync(0xffffffffu, s, o);
    if ((t & 31) == 0) red[t >> 5] = s;
    __syncthreads();
    if (t < 32) {
        float z = (t < 8) ? red[t] : 0.f;
#pragma unroll
        for (int o = 4; o; o >>= 1) z += __shfl_xor_sync(0xffffffffu, z, o);
        if (t == 0) red[0] = z;
    }
    __syncthreads();
    float inv = 1.f / red[0];
#pragma unroll
    for (int i = 0; i < 8; i++) p[t + 256 * i] = v[i] * inv;
}

// ---------------------------------------------------------------------------
// O = attn @ V per (b,h). M=2048, N=64, K=2048. grid (1,16,64)
// Writes O directly in [b, l, h*64+dv] layout.
// ---------------------------------------------------------------------------
__global__ void __launch_bounds__(256) av_kernel(const float* __restrict__ attn,
                                                 const float* __restrict__ v,
                                                 float* __restrict__ o) {
    int z = blockIdx.z;
    int b = z >> 4, h = z & 15;
    const float* A = attn + (size_t)z * LL * LL;
    const float* Bp = v + (size_t)b * LL * DD + h * DKK;
    float* Cp = o + (size_t)b * LL * DD + h * DKK;
    int bm = blockIdx.y * 128;
    __shared__ float As[16][128];
    __shared__ float Bs[16][64];
    int tid = threadIdx.x;
    int tx = tid & 15, ty = tid >> 4;
    float acc[8][4];
#pragma unroll
    for (int i = 0; i < 8; i++)
#pragma unroll
        for (int j = 0; j < 4; j++) acc[i][j] = 0.f;

    for (int k0 = 0; k0 < LL; k0 += 16) {
#pragma unroll
        for (int i = 0; i < 2; i++) {
            int f = tid + i * 256;
            int row = f >> 2;
            int c4 = (f & 3) << 2;
            float4 va = *(const float4*)(A + (size_t)(bm + row) * LL + k0 + c4);
            As[c4 + 0][row] = va.x; As[c4 + 1][row] = va.y;
            As[c4 + 2][row] = va.z; As[c4 + 3][row] = va.w;
        }
        {
            int row = tid >> 4;        // 0..15
            int c4 = (tid & 15) << 2;  // 0..60
            float4 vb = *(const float4*)(Bp + (size_t)(k0 + row) * DD + c4);
            *(float4*)&Bs[row][c4] = vb;
        }
        __syncthreads();
#pragma unroll
        for (int kk = 0; kk < 16; kk++) {
            float4 b0 = *(const float4*)&Bs[kk][tx * 4];
            float4 a0 = *(const float4*)&As[kk][ty * 8];
            float4 a1 = *(const float4*)&As[kk][ty * 8 + 4];
            float a[8] = {a0.x, a0.y, a0.z, a0.w, a1.x, a1.y, a1.z, a1.w};
            float bb[4] = {b0.x, b0.y, b0.z, b0.w};
#pragma unroll
            for (int i = 0; i < 8; i++)
#pragma unroll
                for (int j = 0; j < 4; j++) acc[i][j] += a[i] * bb[j];
        }
        __syncthreads();
    }
#pragma unroll
    for (int i = 0; i < 8; i++) {
        int m = bm + ty * 8 + i;
        float4 w = make_float4(acc[i][0], acc[i][1], acc[i][2], acc[i][3]);
        *(float4*)(Cp + (size_t)m * DD + tx * 4) = w;
    }
}

// ---------------------------------------------------------------------------
// Launch
// ---------------------------------------------------------------------------
extern "C" void kernel_launch(void* const* d_in, const int* in_sizes, int n_in,
                              void* d_out, int out_size) {
    const float* src    = (const float*)d_in[0];
    const int*   mask   = (const int*)d_in[1];
    const float* prior  = (const float*)d_in[2];
    const float* ln1_g  = (const float*)d_in[3];
    const float* ln1_b  = (const float*)d_in[4];
    const float* wq     = (const float*)d_in[5];
    const float* wk     = (const float*)d_in[6];
    const float* wv     = (const float*)d_in[7];
    const float* fc_w   = (const float*)d_in[8];
    const float* ln2_g  = (const float*)d_in[9];
    const float* ln2_b  = (const float*)d_in[10];
    const float* w1_w   = (const float*)d_in[11];
    const float* w1_b   = (const float*)d_in[12];
    const float* w2_w   = (const float*)d_in[13];
    const float* w2_b   = (const float*)d_in[14];

    float* out = (float*)d_out;
    float* y_out = out;
    float* attn_out = out + ATTN_OFF;

    float *x, *q, *k, *v, *o, *y1, *zz, *hh;
    cudaGetSymbolAddress((void**)&x,  g_x);
    cudaGetSymbolAddress((void**)&q,  g_q);
    cudaGetSymbolAddress((void**)&k,  g_k);
    cudaGetSymbolAddress((void**)&v,  g_v);
    cudaGetSymbolAddress((void**)&o,  g_o);
    cudaGetSymbolAddress((void**)&y1, g_y1);
    cudaGetSymbolAddress((void**)&zz, g_z);
    cudaGetSymbolAddress((void**)&hh, g_h);

    // LN1
    ln_kernel<<<MROWS, 256>>>(src, ln1_g, ln1_b, x);

    // QKV projections: [8192,1024] @ [1024,1024]^T
    dim3 gproj(DD / 128, MROWS / 128);
    gemm_abt<0><<<gproj, 256>>>(x, DD, wq, DD, q, DD, DD, nullptr, nullptr, 0);
    gemm_abt<0><<<gproj, 256>>>(x, DD, wk, DD, k, DD, DD, nullptr, nullptr, 0);
    gemm_abt<0><<<gproj, 256>>>(x, DD, wv, DD, v, DD, DD, nullptr, nullptr, 0);

    // Scores + mask + prior -> attn region of d_out
    scores_kernel<<<dim3(LL / 128, LL / 128, BB * HH), 256>>>(q, k, prior, mask, attn_out);

    // Softmax in-place
    softmax_kernel<<<BB * HH * LL, 256>>>(attn_out);

    // O = attn @ V
    av_kernel<<<dim3(1, LL / 128, BB * HH), 256>>>(attn_out, v, o);

    // y1 = O @ fc_w^T + src
    gemm_abt<3><<<gproj, 256>>>(o, DD, fc_w, DD, y1, DD, DD, nullptr, src, DD);

    // LN2
    ln_kernel<<<MROWS, 256>>>(y1, ln2_g, ln2_b, zz);

    // h = relu(z @ w1^T + b1): [8192,4096]
    gemm_abt<1><<<dim3(DFF / 128, MROWS / 128), 256>>>(zz, DD, w1_w, DD, hh, DFF, DD, w1_b, nullptr, 0);

    // y = h @ w2^T + b2 + y1 -> y region of d_out
    gemm_abt<2><<<gproj, 256>>>(hh, DFF, w2_w, DFF, y_out, DD, DFF, w2_b, y1, DD);
}

// round 6
// speedup vs baseline: 2.5957x; 2.5957x over previous
#include <cuda_runtime.h>
#include <cuda_bf16.h>
#include <cstdint>

#define BB 4
#define LL 2048
#define DD 1024
#define HH 16
#define DKK 64
#define DFF 4096
#define MROWS (BB*LL)
#define ATTN_OFF ((size_t)MROWS*DD)
#define PAD 36

// Scratch
__device__ float g_x[(size_t)MROWS*DD];
__device__ float g_q[(size_t)MROWS*DD];
__device__ float g_k[(size_t)MROWS*DD];
__device__ float g_v[(size_t)MROWS*DD];
__device__ float g_o[(size_t)MROWS*DD];
__device__ float g_y1[(size_t)MROWS*DD];
__device__ float g_z[(size_t)MROWS*DD];
__device__ float g_h[(size_t)MROWS*DFF];

__device__ __forceinline__ uint32_t f2t(float x) {
    uint32_t u; asm("cvt.rna.tf32.f32 %0, %1;" : "=r"(u) : "f"(x)); return u;
}
__device__ __forceinline__ void mma8(float* c, const uint32_t* a, const uint32_t* b) {
    asm volatile(
        "mma.sync.aligned.m16n8k8.row.col.f32.tf32.tf32.f32 "
        "{%0,%1,%2,%3},{%4,%5,%6,%7},{%8,%9},{%0,%1,%2,%3};"
        : "+f"(c[0]), "+f"(c[1]), "+f"(c[2]), "+f"(c[3])
        : "r"(a[0]), "r"(a[1]), "r"(a[2]), "r"(a[3]), "r"(b[0]), "r"(b[1]));
}

// ---------------------------------------------------------------------------
// LayerNorm
// ---------------------------------------------------------------------------
__global__ void __launch_bounds__(256) ln_kernel(const float* __restrict__ in,
                                                 const float* __restrict__ gamma,
                                                 const float* __restrict__ beta,
                                                 float* __restrict__ out) {
    int row = blockIdx.x;
    const float* x = in + (size_t)row * DD;
    float* y = out + (size_t)row * DD;
    int t = threadIdx.x;
    float v[4];
    float s = 0.f;
#pragma unroll
    for (int i = 0; i < 4; i++) { v[i] = x[t + 256 * i]; s += v[i]; }
    __shared__ float red[32];
#pragma unroll
    for (int o = 16; o; o >>= 1) s += __shfl_xor_sync(0xffffffffu, s, o);
    if ((t & 31) == 0) red[t >> 5] = s;
    __syncthreads();
    if (t < 32) {
        float z = (t < 8) ? red[t] : 0.f;
#pragma unroll
        for (int o = 4; o; o >>= 1) z += __shfl_xor_sync(0xffffffffu, z, o);
        if (t == 0) red[0] = z;
    }
    __syncthreads();
    float mu = red[0] * (1.f / DD);
    __syncthreads();
    float s2 = 0.f;
#pragma unroll
    for (int i = 0; i < 4; i++) { float d = v[i] - mu; s2 += d * d; }
#pragma unroll
    for (int o = 16; o; o >>= 1) s2 += __shfl_xor_sync(0xffffffffu, s2, o);
    if ((t & 31) == 0) red[t >> 5] = s2;
    __syncthreads();
    if (t < 32) {
        float z = (t < 8) ? red[t] : 0.f;
#pragma unroll
        for (int o = 4; o; o >>= 1) z += __shfl_xor_sync(0xffffffffu, z, o);
        if (t == 0) red[0] = z;
    }
    __syncthreads();
    float rstd = rsqrtf(red[0] * (1.f / DD) + 1e-6f);
#pragma unroll
    for (int i = 0; i < 4; i++) {
        int c = t + 256 * i;
        y[c] = (v[i] - mu) * rstd * gamma[c] + beta[c];
    }
}

// ---------------------------------------------------------------------------
// tf32 tensor-core GEMM: C[M,N] = A[M,K] @ B[N,K]^T
// 128x128 tile, kc=32, 8 warps (4m x 2n), warp tile 32x64.
// EPI: 0 none, 1 relu(acc+bias), 2 acc+bias+res, 3 acc+res
// ---------------------------------------------------------------------------
template <int EPI>
__global__ void __launch_bounds__(256, 2) gemm_tc(
    const float* __restrict__ A, int lda,
    const float* __restrict__ B, int ldb,
    float* __restrict__ C, int ldc, int K,
    const float* __restrict__ bias,
    const float* __restrict__ res, int ldres) {
    int bm = blockIdx.y * 128, bn = blockIdx.x * 128;
    __shared__ uint32_t As[128 * PAD];
    __shared__ uint32_t Bs[128 * PAD];
    int tid = threadIdx.x, lane = tid & 31, warp = tid >> 5;
    int wm = (warp & 3) * 32, wn = (warp >> 2) * 64;
    int lq = lane >> 2, lr = lane & 3;
    float acc[2][8][4];
#pragma unroll
    for (int mi = 0; mi < 2; mi++)
#pragma unroll
        for (int ni = 0; ni < 8; ni++)
#pragma unroll
            for (int j = 0; j < 4; j++) acc[mi][ni][j] = 0.f;

    for (int k0 = 0; k0 < K; k0 += 32) {
#pragma unroll
        for (int i = 0; i < 4; i++) {
            int idx = tid + i * 256;
            int row = idx >> 3, c4 = (idx & 7) << 2;
            float4 va = *(const float4*)(A + (size_t)(bm + row) * lda + k0 + c4);
            As[row * PAD + c4 + 0] = f2t(va.x); As[row * PAD + c4 + 1] = f2t(va.y);
            As[row * PAD + c4 + 2] = f2t(va.z); As[row * PAD + c4 + 3] = f2t(va.w);
            float4 vb = *(const float4*)(B + (size_t)(bn + row) * ldb + k0 + c4);
            Bs[row * PAD + c4 + 0] = f2t(vb.x); Bs[row * PAD + c4 + 1] = f2t(vb.y);
            Bs[row * PAD + c4 + 2] = f2t(vb.z); Bs[row * PAD + c4 + 3] = f2t(vb.w);
        }
        __syncthreads();
#pragma unroll
        for (int ks = 0; ks < 4; ks++) {
            int kk = ks * 8;
            uint32_t af[2][4], bf[8][2];
#pragma unroll
            for (int mi = 0; mi < 2; mi++) {
                int r = wm + mi * 16 + lq;
                af[mi][0] = As[r * PAD + kk + lr];
                af[mi][1] = As[(r + 8) * PAD + kk + lr];
                af[mi][2] = As[r * PAD + kk + lr + 4];
                af[mi][3] = As[(r + 8) * PAD + kk + lr + 4];
            }
#pragma unroll
            for (int ni = 0; ni < 8; ni++) {
                int n = wn + ni * 8 + lq;
                bf[ni][0] = Bs[n * PAD + kk + lr];
                bf[ni][1] = Bs[n * PAD + kk + lr + 4];
            }
#pragma unroll
            for (int mi = 0; mi < 2; mi++)
#pragma unroll
                for (int ni = 0; ni < 8; ni++) mma8(acc[mi][ni], af[mi], bf[ni]);
        }
        __syncthreads();
    }
#pragma unroll
    for (int mi = 0; mi < 2; mi++) {
        int r0 = bm + wm + mi * 16 + lq;
#pragma unroll
        for (int ni = 0; ni < 8; ni++) {
            int col = bn + wn + ni * 8 + 2 * lr;
#pragma unroll
            for (int rr = 0; rr < 2; rr++) {
                int m = r0 + rr * 8;
                float v0 = acc[mi][ni][rr * 2 + 0];
                float v1 = acc[mi][ni][rr * 2 + 1];
                if (EPI == 1) { v0 = fmaxf(v0 + bias[col], 0.f); v1 = fmaxf(v1 + bias[col + 1], 0.f); }
                if (EPI == 2) {
                    v0 += bias[col] + res[(size_t)m * ldres + col];
                    v1 += bias[col + 1] + res[(size_t)m * ldres + col + 1];
                }
                if (EPI == 3) {
                    v0 += res[(size_t)m * ldres + col];
                    v1 += res[(size_t)m * ldres + col + 1];
                }
                *(float2*)(C + (size_t)m * ldc + col) = make_float2(v0, v1);
            }
        }
    }
}

// ---------------------------------------------------------------------------
// Scores: per (b,h) S = (Q K^T)/8 * prior, mask. tf32 MMA. grid (16,16,64)
// ---------------------------------------------------------------------------
__global__ void __launch_bounds__(256, 2) scores_tc(
    const float* __restrict__ q, const float* __restrict__ k,
    const float* __restrict__ prior, const int* __restrict__ mask,
    float* __restrict__ attn) {
    int z = blockIdx.z;
    int b = z >> 4, h = z & 15;
    const float* A = q + (size_t)b * LL * DD + h * DKK;
    const float* B = k + (size_t)b * LL * DD + h * DKK;
    float* Cp = attn + (size_t)z * LL * LL;
    int bm = blockIdx.y * 128, bn = blockIdx.x * 128;
    __shared__ uint32_t As[128 * PAD];
    __shared__ uint32_t Bs[128 * PAD];
    int tid = threadIdx.x, lane = tid & 31, warp = tid >> 5;
    int wm = (warp & 3) * 32, wn = (warp >> 2) * 64;
    int lq = lane >> 2, lr = lane & 3;
    float acc[2][8][4];
#pragma unroll
    for (int mi = 0; mi < 2; mi++)
#pragma unroll
        for (int ni = 0; ni < 8; ni++)
#pragma unroll
            for (int j = 0; j < 4; j++) acc[mi][ni][j] = 0.f;

    for (int k0 = 0; k0 < DKK; k0 += 32) {
#pragma unroll
        for (int i = 0; i < 4; i++) {
            int idx = tid + i * 256;
            int row = idx >> 3, c4 = (idx & 7) << 2;
            float4 va = *(const float4*)(A + (size_t)(bm + row) * DD + k0 + c4);
            As[row * PAD + c4 + 0] = f2t(va.x); As[row * PAD + c4 + 1] = f2t(va.y);
            As[row * PAD + c4 + 2] = f2t(va.z); As[row * PAD + c4 + 3] = f2t(va.w);
            float4 vb = *(const float4*)(B + (size_t)(bn + row) * DD + k0 + c4);
            Bs[row * PAD + c4 + 0] = f2t(vb.x); Bs[row * PAD + c4 + 1] = f2t(vb.y);
            Bs[row * PAD + c4 + 2] = f2t(vb.z); Bs[row * PAD + c4 + 3] = f2t(vb.w);
        }
        __syncthreads();
#pragma unroll
        for (int ks = 0; ks < 4; ks++) {
            int kk = ks * 8;
            uint32_t af[2][4], bf[8][2];
#pragma unroll
            for (int mi = 0; mi < 2; mi++) {
                int r = wm + mi * 16 + lq;
                af[mi][0] = As[r * PAD + kk + lr];
                af[mi][1] = As[(r + 8) * PAD + kk + lr];
                af[mi][2] = As[r * PAD + kk + lr + 4];
                af[mi][3] = As[(r + 8) * PAD + kk + lr + 4];
            }
#pragma unroll
            for (int ni = 0; ni < 8; ni++) {
                int n = wn + ni * 8 + lq;
                bf[ni][0] = Bs[n * PAD + kk + lr];
                bf[ni][1] = Bs[n * PAD + kk + lr + 4];
            }
#pragma unroll
            for (int mi = 0; mi < 2; mi++)
#pragma unroll
                for (int ni = 0; ni < 8; ni++) mma8(acc[mi][ni], af[mi], bf[ni]);
        }
        __syncthreads();
    }
#pragma unroll
    for (int mi = 0; mi < 2; mi++) {
        int r0 = bm + wm + mi * 16 + lq;
#pragma unroll
        for (int ni = 0; ni < 8; ni++) {
            int col = bn + wn + ni * 8 + 2 * lr;
            int m0 = mask[b * LL + col], m1 = mask[b * LL + col + 1];
#pragma unroll
            for (int rr = 0; rr < 2; rr++) {
                int m = r0 + rr * 8;
                const float* prow = prior + ((size_t)b * LL + m) * LL + col;
                float v0 = acc[mi][ni][rr * 2 + 0] * 0.125f * prow[0];
                float v1 = acc[mi][ni][rr * 2 + 1] * 0.125f * prow[1];
                if (m0 == 0) v0 = -1e9f;
                if (m1 == 0) v1 = -1e9f;
                *(float2*)(Cp + (size_t)m * LL + col) = make_float2(v0, v1);
            }
        }
    }
}

// ---------------------------------------------------------------------------
// Softmax
// ---------------------------------------------------------------------------
__global__ void __launch_bounds__(256) softmax_kernel(float* __restrict__ attn) {
    size_t row = blockIdx.x;
    float* p = attn + row * LL;
    int t = threadIdx.x;
    float v[8];
    float mx = -3.4e38f;
#pragma unroll
    for (int i = 0; i < 8; i++) { v[i] = p[t + 256 * i]; mx = fmaxf(mx, v[i]); }
    __shared__ float red[32];
#pragma unroll
    for (int o = 16; o; o >>= 1) mx = fmaxf(mx, __shfl_xor_sync(0xffffffffu, mx, o));
    if ((t & 31) == 0) red[t >> 5] = mx;
    __syncthreads();
    if (t < 32) {
        float z = (t < 8) ? red[t] : -3.4e38f;
#pragma unroll
        for (int o = 4; o; o >>= 1) z = fmaxf(z, __shfl_xor_sync(0xffffffffu, z, o));
        if (t == 0) red[0] = z;
    }
    __syncthreads();
    mx = red[0];
    __syncthreads();
    float s = 0.f;
#pragma unroll
    for (int i = 0; i < 8; i++) { v[i] = expf(v[i] - mx); s += v[i]; }
#pragma unroll
    for (int o = 16; o; o >>= 1) s += __shfl_xor_sync(0xffffffffu, s, o);
    if ((t & 31) == 0) red[t >> 5] = s;
    __syncthreads();
    if (t < 32) {
        float z = (t < 8) ? red[t] : 0.f;
#pragma unroll
        for (int o = 4; o; o >>= 1) z += __shfl_xor_sync(0xffffffffu, z, o);
        if (t == 0) red[0] = z;
    }
    __syncthreads();
    float inv = 1.f / red[0];
#pragma unroll
    for (int i = 0; i < 8; i++) p[t + 256 * i] = v[i] * inv;
}

// ---------------------------------------------------------------------------
// AV: O = attn @ V per (b,h). M=2048, N=64, K=2048. tf32 MMA. grid (1,16,64)
// ---------------------------------------------------------------------------
#define VPAD 68
__global__ void __launch_bounds__(256, 2) av_tc(const float* __restrict__ attn,
                                                const float* __restrict__ v,
                                                float* __restrict__ o) {
    int z = blockIdx.z;
    int b = z >> 4, h = z & 15;
    const float* A = attn + (size_t)z * LL * LL;
    const float* Vp = v + (size_t)b * LL * DD + h * DKK;
    float* Cp = o + (size_t)b * LL * DD + h * DKK;
    int bm = blockIdx.y * 128;
    __shared__ uint32_t As[128 * PAD];
    __shared__ uint32_t Bs[32 * VPAD];
    int tid = threadIdx.x, lane = tid & 31, warp = tid >> 5;
    int wm = warp * 16;
    int lq = lane >> 2, lr = lane & 3;
    float acc[8][4];
#pragma unroll
    for (int ni = 0; ni < 8; ni++)
#pragma unroll
        for (int j = 0; j < 4; j++) acc[ni][j] = 0.f;

    for (int k0 = 0; k0 < LL; k0 += 32) {
#pragma unroll
        for (int i = 0; i < 4; i++) {
            int idx = tid + i * 256;
            int row = idx >> 3, c4 = (idx & 7) << 2;
            float4 va = *(const float4*)(A + (size_t)(bm + row) * LL + k0 + c4);
            As[row * PAD + c4 + 0] = f2t(va.x); As[row * PAD + c4 + 1] = f2t(va.y);
            As[row * PAD + c4 + 2] = f2t(va.z); As[row * PAD + c4 + 3] = f2t(va.w);
        }
#pragma unroll
        for (int i = 0; i < 2; i++) {
            int idx = tid + i * 256;          // 0..511
            int krow = idx >> 4, c4 = (idx & 15) << 2;
            float4 vb = *(const float4*)(Vp + (size_t)(k0 + krow) * DD + c4);
            Bs[krow * VPAD + c4 + 0] = f2t(vb.x); Bs[krow * VPAD + c4 + 1] = f2t(vb.y);
            Bs[krow * VPAD + c4 + 2] = f2t(vb.z); Bs[krow * VPAD + c4 + 3] = f2t(vb.w);
        }
        __syncthreads();
#pragma unroll
        for (int ks = 0; ks < 4; ks++) {
            int kk = ks * 8;
            uint32_t af[4], bf[8][2];
            int r = wm + lq;
            af[0] = As[r * PAD + kk + lr];
            af[1] = As[(r + 8) * PAD + kk + lr];
            af[2] = As[r * PAD + kk + lr + 4];
            af[3] = As[(r + 8) * PAD + kk + lr + 4];
#pragma unroll
            for (int ni = 0; ni < 8; ni++) {
                int n = ni * 8 + lq;
                bf[ni][0] = Bs[(kk + lr) * VPAD + n];
                bf[ni][1] = Bs[(kk + lr + 4) * VPAD + n];
            }
#pragma unroll
            for (int ni = 0; ni < 8; ni++) mma8(acc[ni], af, bf[ni]);
        }
        __syncthreads();
    }
    int r0 = bm + wm + lq;
#pragma unroll
    for (int ni = 0; ni < 8; ni++) {
        int col = ni * 8 + 2 * lr;
#pragma unroll
        for (int rr = 0; rr < 2; rr++) {
            int m = r0 + rr * 8;
            *(float2*)(Cp + (size_t)m * DD + col) =
                make_float2(acc[ni][rr * 2 + 0], acc[ni][rr * 2 + 1]);
        }
    }
}

// ---------------------------------------------------------------------------
// Launch
// ---------------------------------------------------------------------------
extern "C" void kernel_launch(void* const* d_in, const int* in_sizes, int n_in,
                              void* d_out, int out_size) {
    const float* src    = (const float*)d_in[0];
    const int*   mask   = (const int*)d_in[1];
    const float* prior  = (const float*)d_in[2];
    const float* ln1_g  = (const float*)d_in[3];
    const float* ln1_b  = (const float*)d_in[4];
    const float* wq     = (const float*)d_in[5];
    const float* wk     = (const float*)d_in[6];
    const float* wv     = (const float*)d_in[7];
    const float* fc_w   = (const float*)d_in[8];
    const float* ln2_g  = (const float*)d_in[9];
    const float* ln2_b  = (const float*)d_in[10];
    const float* w1_w   = (const float*)d_in[11];
    const float* w1_b   = (const float*)d_in[12];
    const float* w2_w   = (const float*)d_in[13];
    const float* w2_b   = (const float*)d_in[14];

    float* out = (float*)d_out;
    float* y_out = out;
    float* attn_out = out + ATTN_OFF;

    float *x, *q, *k, *v, *o, *y1, *zz, *hh;
    cudaGetSymbolAddress((void**)&x,  g_x);
    cudaGetSymbolAddress((void**)&q,  g_q);
    cudaGetSymbolAddress((void**)&k,  g_k);
    cudaGetSymbolAddress((void**)&v,  g_v);
    cudaGetSymbolAddress((void**)&o,  g_o);
    cudaGetSymbolAddress((void**)&y1, g_y1);
    cudaGetSymbolAddress((void**)&zz, g_z);
    cudaGetSymbolAddress((void**)&hh, g_h);

    ln_kernel<<<MROWS, 256>>>(src, ln1_g, ln1_b, x);

    dim3 gproj(DD / 128, MROWS / 128);
    gemm_tc<0><<<gproj, 256>>>(x, DD, wq, DD, q, DD, DD, nullptr, nullptr, 0);
    gemm_tc<0><<<gproj, 256>>>(x, DD, wk, DD, k, DD, DD, nullptr, nullptr, 0);
    gemm_tc<0><<<gproj, 256>>>(x, DD, wv, DD, v, DD, DD, nullptr, nullptr, 0);

    scores_tc<<<dim3(LL / 128, LL / 128, BB * HH), 256>>>(q, k, prior, mask, attn_out);

    softmax_kernel<<<BB * HH * LL, 256>>>(attn_out);

    av_tc<<<dim3(1, LL / 128, BB * HH), 256>>>(attn_out, v, o);

    gemm_tc<3><<<gproj, 256>>>(o, DD, fc_w, DD, y1, DD, DD, nullptr, src, DD);

    ln_kernel<<<MROWS, 256>>>(y1, ln2_g, ln2_b, zz);

    gemm_tc<1><<<dim3(DFF / 128, MROWS / 128), 256>>>(zz, DD, w1_w, DD, hh, DFF, DD, w1_b, nullptr, 0);

    gemm_tc<2><<<gproj, 256>>>(hh, DFF, w2_w, DFF, y_out, DD, DFF, w2_b, y1, DD);
}